// round 1
// baseline (speedup 1.0000x reference)
#include <cuda_runtime.h>

// Problem constants (fixed shapes per metadata):
// depths (2,2,1,512,512) colors (2,2,3,512,512) feats (2,2,64,256,256)
// K (2,4,4) src_RTs/src_RTinvs (2,2,4,4) dst_RTs/dst_RTinvs (2,1,4,4)
#define HWF 65536      // 256*256
#define HWC 262144     // 512*512
#define NBV 4          // B*V
#define OFF_WARPED 16777216            // 2*2*64*HWF
#define OFF_DEPTH  17563648            // + 2*2*3*HWF

// Scratch (allocation-free: __device__ globals)
__device__ float g_M[NBV][4][16];                 // sKinv, srcRTinv, dstRT, sK per (b,v)
__device__ unsigned long long g_zw[NBV * HWF];    // packed (z_bits<<32)|point_id
__device__ float g_col[NBV * 3 * HWF];            // resized colors *0.5+0.5

// ---------------- setup: per-batch matrices, sK inverse in double ----------------
__global__ void k_setup(const float* __restrict__ Kmat,
                        const float* __restrict__ srcRTinv,
                        const float* __restrict__ dstRT) {
    if (blockIdx.x || threadIdx.x) return;
    for (int b = 0; b < 2; ++b) {
        float sK[16];
        const float scale[4] = {0.5f, 0.5f, 1.0f, 1.0f};  // (Wf/Wc, Hf/Hc, 1, 1) on rows
        for (int r = 0; r < 4; ++r)
            for (int c = 0; c < 4; ++c)
                sK[r * 4 + c] = __fmul_rn(Kmat[b * 16 + r * 4 + c], scale[r]);
        // Gauss-Jordan inverse (double) — exact for the diag/power-of-2 K given
        double a[4][8];
        for (int r = 0; r < 4; ++r)
            for (int c = 0; c < 4; ++c) { a[r][c] = (double)sK[r * 4 + c]; a[r][4 + c] = (r == c) ? 1.0 : 0.0; }
        for (int col = 0; col < 4; ++col) {
            int piv = col;
            for (int r = col + 1; r < 4; ++r) if (fabs(a[r][col]) > fabs(a[piv][col])) piv = r;
            if (piv != col) for (int j = 0; j < 8; ++j) { double t = a[col][j]; a[col][j] = a[piv][j]; a[piv][j] = t; }
            double inv = 1.0 / a[col][col];
            for (int j = 0; j < 8; ++j) a[col][j] *= inv;
            for (int r = 0; r < 4; ++r) if (r != col) {
                double f = a[r][col];
                for (int j = 0; j < 8; ++j) a[r][j] -= f * a[col][j];
            }
        }
        float sKi[16];
        for (int r = 0; r < 4; ++r) for (int c = 0; c < 4; ++c) sKi[r * 4 + c] = (float)a[r][4 + c];
        for (int v = 0; v < 2; ++v) {
            int bv = b * 2 + v;
            for (int i = 0; i < 16; ++i) {
                g_M[bv][0][i] = sKi[i];
                g_M[bv][1][i] = srcRTinv[bv * 16 + i];
                g_M[bv][2][i] = dstRT[b * 16 + i];   // dst_RTs[:,0]
                g_M[bv][3][i] = sK[i];
            }
        }
    }
}

// ---------------- init z/winner buffer ----------------
__global__ void __launch_bounds__(256) k_init() {
    int t = blockIdx.x * 256 + threadIdx.x;
    if (t < NBV * HWF)
        g_zw[t] = ((unsigned long long)__float_as_uint(1e10f) << 32) | 65536ull;
}

// staged 4x4 matvec, ascending-j, no fma (mirror XLA einsum)
__device__ __forceinline__ void mv4(const float* __restrict__ M, const float* v, float* o) {
#pragma unroll
    for (int i = 0; i < 4; ++i) {
        float acc = __fmul_rn(M[i * 4 + 0], v[0]);
        acc = __fadd_rn(acc, __fmul_rn(M[i * 4 + 1], v[1]));
        acc = __fadd_rn(acc, __fmul_rn(M[i * 4 + 2], v[2]));
        acc = __fadd_rn(acc, __fmul_rn(M[i * 4 + 3], v[3]));
        o[i] = acc;
    }
}

// ---------------- project + splat (single fused winner pass) ----------------
__global__ void __launch_bounds__(256) k_points(const float* __restrict__ depths) {
    int t = blockIdx.x * 256 + threadIdx.x;
    if (t >= NBV * HWF) return;
    int bv = t >> 16;
    int p = t & 65535;
    int y = p >> 8, x = p & 255;

    // nearest-resize depth: jax picks input index floor((i+0.5)*2) = 2i+1
    float d = depths[(size_t)bv * HWC + (2 * y + 1) * 512 + (2 * x + 1)];

    // jnp.linspace(-1,1,256): start + i*delta, endpoint forced exact
    float dl = __fdiv_rn(2.0f, 255.0f);
    float gx = (x == 255) ? 1.0f : __fadd_rn(__fmul_rn((float)x, dl), -1.0f);
    float gy = (y == 255) ? 1.0f : __fadd_rn(__fmul_rn((float)y, dl), -1.0f);

    float proj[4] = { __fmul_rn(gx, d), __fmul_rn(gy, d), d, 1.0f };
    const float* M = &g_M[bv][0][0];
    float cam[4], world[4], cam2[4], xyp[4];
    mv4(M,      proj,  cam);    // sKinv @ proj
    mv4(M + 16, cam,   world);  // srcRTinv @ cam
    mv4(M + 32, world, cam2);   // dstRT @ world
    mv4(M + 48, cam2,  xyp);    // sK @ cam2

    float z = xyp[2];
    float sx, sy, sz;
    if (fabsf(z) < 1e-4f) { sx = -10.0f; sy = -10.0f; sz = -10.0f; }
    else { sx = __fdiv_rn(xyp[0], z); sy = __fdiv_rn(xyp[1], z); sz = z; }

    float pxf = __fmul_rn(__fmul_rn(__fadd_rn(sx, 1.0f), 0.5f), 255.0f);
    float pyf = __fmul_rn(__fmul_rn(__fadd_rn(sy, 1.0f), 0.5f), 255.0f);
    int px = __float2int_rn(pxf);   // half-even, matches jnp.round
    int py = __float2int_rn(pyf);

    if (px >= 0 && px < 256 && py >= 0 && py < 256 && sz > 1e-4f) {
        // lexicographic (z, pid) min == reference's zbuf-min + min-index tiebreak
        unsigned long long pack = ((unsigned long long)__float_as_uint(sz) << 32) | (unsigned)p;
        atomicMin(&g_zw[bv * HWF + py * 256 + px], pack);
    }
}

// ---------------- antialiased linear 2x downsample of colors ----------------
__device__ __forceinline__ void aa_w(int i, int n_in, int* j0, float* w) {
    *j0 = 2 * i - 1;
    w[0] = 0.25f; w[1] = 0.75f; w[2] = 0.75f; w[3] = 0.25f;
    float s = 0.0f;
#pragma unroll
    for (int t = 0; t < 4; ++t) {
        int j = *j0 + t;
        if (j < 0 || j >= n_in) w[t] = 0.0f;
        s += w[t];
    }
    float inv = __fdiv_rn(1.0f, s);
#pragma unroll
    for (int t = 0; t < 4; ++t) w[t] *= inv;
}

__global__ void __launch_bounds__(256) k_resize(const float* __restrict__ colors) {
    int t = blockIdx.x * 256 + threadIdx.x;
    if (t >= NBV * HWF) return;
    int bv = t >> 16;
    int p = t & 65535;
    int y = p >> 8, x = p & 255;
    int jy0, jx0;
    float wy[4], wx[4];
    aa_w(y, 512, &jy0, wy);
    aa_w(x, 512, &jx0, wx);
    const float* src = colors + (size_t)bv * 3 * HWC;
#pragma unroll
    for (int c = 0; c < 3; ++c) {
        float acc = 0.0f;
#pragma unroll
        for (int ty = 0; ty < 4; ++ty) {
            int sy = min(max(jy0 + ty, 0), 511);
            float row = 0.0f;
#pragma unroll
            for (int tx = 0; tx < 4; ++tx) {
                int sxx = min(max(jx0 + tx, 0), 511);
                row += wx[tx] * __ldg(&src[(size_t)c * HWC + sy * 512 + sxx]);
            }
            acc += wy[ty] * row;
        }
        g_col[(size_t)bv * 3 * HWF + c * HWF + p] = acc * 0.5f + 0.5f;
    }
}

// ---------------- gather winners into outputs ----------------
__global__ void __launch_bounds__(256) k_gather(const float* __restrict__ feats,
                                                float* __restrict__ out) {
    int t = blockIdx.x * 256 + threadIdx.x;
    if (t >= NBV * HWF) return;
    int bv = t >> 16;
    int p = t & 65535;
    unsigned long long zw = g_zw[t];
    unsigned w = (unsigned)(zw & 0xffffffffull);
    unsigned zb = (unsigned)(zw >> 32);
    bool has = w < 65536u;

    // prj_fs: (B,V,C,H,W)
    const float* fsrc = feats + (size_t)bv * 64 * HWF;
    float* pf = out + (size_t)bv * 64 * HWF;
#pragma unroll 8
    for (int c = 0; c < 64; ++c)
        pf[(size_t)c * HWF + p] = has ? __ldg(&fsrc[(size_t)c * HWF + w]) : 0.0f;

    // warped: (V,B,3,H,W)  (reference does NOT transpose this one)
    int b = bv >> 1, v = bv & 1;
    const float* csrc = g_col + (size_t)bv * 3 * HWF;
    float* wp = out + OFF_WARPED + (size_t)(v * 2 + b) * 3 * HWF;
#pragma unroll
    for (int c = 0; c < 3; ++c)
        wp[(size_t)c * HWF + p] = has ? csrc[(size_t)c * HWF + w] : 0.0f;

    // prj_depths: (B,V,1,H,W)
    float z = __uint_as_float(zb);
    out[OFF_DEPTH + (size_t)bv * HWF + p] = (z < 1e10f) ? z : 0.0f;
}

extern "C" void kernel_launch(void* const* d_in, const int* in_sizes, int n_in,
                              void* d_out, int out_size) {
    const float* depths   = (const float*)d_in[0];
    const float* colors   = (const float*)d_in[1];
    const float* feats    = (const float*)d_in[2];
    const float* Kmat     = (const float*)d_in[3];
    const float* srcRTinv = (const float*)d_in[5];
    const float* dstRT    = (const float*)d_in[6];
    float* out = (float*)d_out;

    const int n = NBV * HWF;
    const int nb = n / 256;
    k_setup<<<1, 1>>>(Kmat, srcRTinv, dstRT);
    k_init<<<nb, 256>>>();
    k_points<<<nb, 256>>>(depths);
    k_resize<<<nb, 256>>>(colors);
    k_gather<<<nb, 256>>>(feats, out);
}